// round 6
// baseline (speedup 1.0000x reference)
#include <cuda_runtime.h>

#define C_DIM 4096
#define N_F 8
#define NPAIR 36            // 8*9/2, i<=j
#define EPS_F 1e-8f
#define NTILE 32            // 4096 / 128
#define NCROSS 528          // NTILE*(NTILE+1)/2 triangle tiles
#define NSORT 8             // one sort block per factor
#define NBLOCKS (NCROSS + NSORT)

// Scratch (device globals; no allocation allowed).
__device__ float g_rowsum[N_F * C_DIM];      // rowsum[f][u] = sum_v |x_fu - x_fv|
__device__ float g_parts[NCROSS][NPAIR];     // per-tile cross partials
__device__ float g_fsum[N_F];                // sum_u rowsum[f][u]
__device__ float g_stot[2 * NPAIR];          // [0,36): rowdots  [36,72): cross
__device__ unsigned int g_ctr2 = 0;          // epilogue ticket (reset each replay)

// ============================ main kernel ============================
// blocks [0, 528):   cross-product tiles over the upper triangle (scalar, R4-proven)
// blocks [528, 536): per-factor sort + prefix rowsum (O(C log C), exact)
__global__ __launch_bounds__(128) void main_kernel(const float* __restrict__ x) {
    __shared__ union {
        struct {
            float v[128][N_F];      // v-tile values [vi][f], 4 KB
            float red[4][NPAIR];    // per-warp cross partials
        } c;
        struct {
            float sv[C_DIM];        // values (sorted in place), 16 KB
            int   si[C_DIM];        // original indices, 16 KB
            float csum[128];        // per-thread chunk partials
        } s;
    } sh;

    const int tid = threadIdx.x;
    const int bid = blockIdx.x;

    // Block 0 zeroes the epilogue accumulators (epilogue runs in a later launch).
    if (bid == 0 && tid < 2 * NPAIR) g_stot[tid] = 0.0f;

    if (bid < NCROSS) {
        // ---------------- cross path: tile (ti, tj), ti <= tj ----------------
        int rem = bid, ti = 0;
        while (rem >= NTILE - ti) { rem -= NTILE - ti; ti++; }
        const int tj = ti + rem;

        for (int i = tid; i < 128 * N_F; i += 128) {
            int f = i >> 7, vi = i & 127;
            sh.c.v[vi][f] = x[f * C_DIM + tj * 128 + vi];
        }

        const int u = ti * 128 + tid;
        float xu[N_F];
#pragma unroll
        for (int f = 0; f < N_F; f++) xu[f] = x[f * C_DIM + u];

        __syncthreads();

        float acc[NPAIR];
#pragma unroll
        for (int k = 0; k < NPAIR; k++) acc[k] = 0.0f;

#pragma unroll 2
        for (int vi = 0; vi < 128; vi++) {
            float4 p0 = *reinterpret_cast<const float4*>(&sh.c.v[vi][0]);
            float4 p1 = *reinterpret_cast<const float4*>(&sh.c.v[vi][4]);
            float xv[N_F] = {p0.x, p0.y, p0.z, p0.w, p1.x, p1.y, p1.z, p1.w};

            float a[N_F];
#pragma unroll
            for (int f = 0; f < N_F; f++) a[f] = fabsf(xu[f] - xv[f]);

            int k = 0;
#pragma unroll
            for (int i = 0; i < N_F; i++)
#pragma unroll
                for (int j = i; j < N_F; j++) {
                    acc[k] = fmaf(a[i], a[j], acc[k]);
                    k++;
                }
        }

        // Diagonal tiles internally symmetric: weight 0.5 so each unordered
        // pair u<v counts exactly once across all tiles (self terms are 0).
        const float w = (ti == tj) ? 0.5f : 1.0f;
        const int lane = tid & 31;
        const int warp = tid >> 5;
#pragma unroll
        for (int k = 0; k < NPAIR; k++) {
            float v = acc[k];
            for (int o = 16; o; o >>= 1) v += __shfl_down_sync(0xffffffffu, v, o);
            if (lane == 0) sh.c.red[warp][k] = v * w;
        }
        __syncthreads();
        if (tid < NPAIR) {
            g_parts[bid][tid] =
                sh.c.red[0][tid] + sh.c.red[1][tid] + sh.c.red[2][tid] + sh.c.red[3][tid];
        }
    } else {
        // ---------------- sort path: factor f ----------------
        // rowsum(rank r) = s_r*(2r - C) + Total - 2*P_excl(r)   (exact)
        const int f = bid - NCROSS;
        const float* xf = x + f * C_DIM;

        for (int i = tid; i < C_DIM; i += 128) {
            sh.s.sv[i] = xf[i];
            sh.s.si[i] = i;
        }
        __syncthreads();

        // Bitonic sort, ascending, key=value payload=index.
        for (int k = 2; k <= C_DIM; k <<= 1) {
            for (int j = k >> 1; j > 0; j >>= 1) {
                for (int t = tid; t < C_DIM / 2; t += 128) {
                    int a = ((t & ~(j - 1)) << 1) | (t & (j - 1));
                    int b = a | j;
                    bool up = ((a & k) == 0);
                    float va = sh.s.sv[a], vb = sh.s.sv[b];
                    bool sw = up ? (va > vb) : (va < vb);
                    if (sw) {
                        sh.s.sv[a] = vb; sh.s.sv[b] = va;
                        int ia = sh.s.si[a], ib = sh.s.si[b];
                        sh.s.si[a] = ib; sh.s.si[b] = ia;
                    }
                }
                __syncthreads();
            }
        }

        // Per-thread chunk sums (32 consecutive sorted values each).
        const int base = tid * 32;
        float cs = 0.0f;
        for (int r = base; r < base + 32; r++) cs += sh.s.sv[r];
        sh.s.csum[tid] = cs;
        __syncthreads();

        float off = 0.0f, total = 0.0f;
        for (int t = 0; t < 128; t++) {
            float c = sh.s.csum[t];
            if (t < tid) off += c;
            total += c;
        }

        // Scatter rowsums; accumulate per-thread rowsum total.
        float run = off, rpart = 0.0f;
        for (int r = base; r < base + 32; r++) {
            float s = sh.s.sv[r];
            float rw = s * (float)(2 * r - C_DIM) + total - 2.0f * run;
            g_rowsum[f * C_DIM + sh.s.si[r]] = rw;
            rpart += rw;
            run += s;
        }
        __syncthreads();
        sh.s.csum[tid] = rpart;
        __syncthreads();
        if (tid == 0) {
            float tt = 0.0f;
            for (int t = 0; t < 128; t++) tt += sh.s.csum[t];
            g_fsum[f] = tt;
        }
    }
}

// ============================ epilogue kernel ============================
// 17 blocks: [0,16) rowsum dots over 256 u's each; block 16 cross partials.
// Last block to finish does the 8x8 dcov/ratio math (mini-ticket).
__global__ __launch_bounds__(256) void reduce_kernel(float* __restrict__ out) {
    __shared__ float red[8][NPAIR];
    __shared__ bool sh_last;
    const int tid = threadIdx.x;
    const int lane = tid & 31;
    const int warp = tid >> 5;

    if (blockIdx.x < 16) {
        const int u = blockIdx.x * 256 + tid;
        float r[N_F];
#pragma unroll
        for (int f = 0; f < N_F; f++) r[f] = g_rowsum[f * C_DIM + u];
        float dot[NPAIR];
        int k = 0;
#pragma unroll
        for (int i = 0; i < N_F; i++)
#pragma unroll
            for (int j = i; j < N_F; j++) {
                dot[k] = r[i] * r[j];
                k++;
            }
#pragma unroll
        for (int kk = 0; kk < NPAIR; kk++) {
            float v = dot[kk];
            for (int o = 16; o; o >>= 1) v += __shfl_down_sync(0xffffffffu, v, o);
            if (lane == 0) red[warp][kk] = v;
        }
        __syncthreads();
        if (tid < NPAIR) {
            float v = 0.0f;
#pragma unroll
            for (int w = 0; w < 8; w++) v += red[w][tid];
            atomicAdd(&g_stot[tid], v);
        }
    } else {
        float cl[NPAIR];
#pragma unroll
        for (int kk = 0; kk < NPAIR; kk++) cl[kk] = 0.0f;
        for (int b = tid; b < NCROSS; b += 256) {
#pragma unroll
            for (int kk = 0; kk < NPAIR; kk++) cl[kk] += g_parts[b][kk];
        }
#pragma unroll
        for (int kk = 0; kk < NPAIR; kk++) {
            float v = cl[kk];
            for (int o = 16; o; o >>= 1) v += __shfl_down_sync(0xffffffffu, v, o);
            if (lane == 0) red[warp][kk] = v;
        }
        __syncthreads();
        if (tid < NPAIR) {
            float v = 0.0f;
#pragma unroll
            for (int w = 0; w < 8; w++) v += red[w][tid];
            atomicAdd(&g_stot[NPAIR + tid], v);
        }
    }

    __syncthreads();
    if (tid == 0) {
        __threadfence();
        sh_last = (atomicAdd(&g_ctr2, 1) == 16u);
    }
    __syncthreads();
    if (!sh_last || tid != 0) return;

    // Final 8x8 math (single thread; bypass L1 for cross-SM atomic results).
    const float fC = (float)C_DIM;
    const float invC2 = 1.0f / (fC * fC);

    float m[N_F];
#pragma unroll
    for (int f = 0; f < N_F; f++) m[f] = __ldcg(&g_fsum[f]) * invC2;

    // S[i][j] = 2*cross_tri/C^2 - 2*rowdot/C^3 + m_i*m_j
    float dcov[N_F][N_F];
    int k = 0;
    for (int i = 0; i < N_F; i++) {
        for (int j = i; j < N_F; j++) {
            float s = 2.0f * __ldcg(&g_stot[NPAIR + k]) * invC2
                    - 2.0f * __ldcg(&g_stot[k]) * invC2 / fC
                    + m[i] * m[j];
            float dc = sqrtf(fmaxf(s, 0.0f) + EPS_F);
            dcov[i][j] = dc;
            dcov[j][i] = dc;
            k++;
        }
    }

    float cor = 0.0f;
    for (int i = 0; i < N_F; i++)
        for (int j = i + 1; j < N_F; j++)
            cor += dcov[i][j] / sqrtf(dcov[i][i] * dcov[j][j] + EPS_F);

    out[0] = cor;
    g_ctr2 = 0;   // reset ticket for graph replay
}

extern "C" void kernel_launch(void* const* d_in, const int* in_sizes, int n_in,
                              void* d_out, int out_size) {
    const float* x = (const float*)d_in[0];
    float* out = (float*)d_out;

    main_kernel<<<NBLOCKS, 128>>>(x);
    reduce_kernel<<<17, 256>>>(out);
}

// round 7
// speedup vs baseline: 2.6548x; 2.6548x over previous
#include <cuda_runtime.h>

#define C_DIM 4096
#define N_F 8
#define NPAIR 36            // 8*9/2, i<=j
#define EPS_F 1e-8f
#define NTILE 32            // 4096 / 128
#define NCROSSB (528 * 2)   // 1056: triangle tiles x 2 v-halves
#define NROWB (8 * 32 * 2)  // 512: (factor, u-tile, v-half)
#define NBLOCKS (NCROSSB + NROWB)
#define NSTOT (2 * NPAIR + N_F)  // [0,36): rowdots  [36,72): cross  [72,80): fsum

// Scratch (device globals; statics start zero; winner block re-zeroes for replay).
__device__ float g_rowsum2[2][N_F * C_DIM];  // halved rowsums (fully overwritten)
__device__ float g_stot[NSTOT];              // global accumulators
__device__ unsigned int g_ctr = 0;           // epilogue ticket

// ============================ main kernel ============================
// blocks [0, 1056):     cross tiles (ti<=tj) x v-half, scalar FFMA (R4-proven)
// blocks [1056, 1568):  rowsum (f, u-tile, v-half)
__global__ __launch_bounds__(128) void main_kernel(const float* __restrict__ x) {
    __shared__ union {
        struct {
            float v[64][N_F];       // v-half values [vi][f], 2 KB
            float red[4][NPAIR];    // per-warp cross partials
        } c;
        float row[2048];            // negated v-half (rowsum path), 8 KB
    } sh;

    const int tid = threadIdx.x;
    const int bid = blockIdx.x;

    if (bid < NCROSSB) {
        // ---------------- cross path ----------------
        const int ci = bid >> 1;
        const int half = bid & 1;
        int rem = ci, ti = 0;
        while (rem >= NTILE - ti) { rem -= NTILE - ti; ti++; }
        const int tj = ti + rem;
        const int vb = tj * 128 + half * 64;

        for (int i = tid; i < 64 * N_F; i += 128) {
            int f = i >> 6, vi = i & 63;
            sh.c.v[vi][f] = x[f * C_DIM + vb + vi];
        }

        const int u = ti * 128 + tid;
        float xu[N_F];
#pragma unroll
        for (int f = 0; f < N_F; f++) xu[f] = x[f * C_DIM + u];

        __syncthreads();

        float acc[NPAIR];
#pragma unroll
        for (int k = 0; k < NPAIR; k++) acc[k] = 0.0f;

#pragma unroll 2
        for (int vi = 0; vi < 64; vi++) {
            float4 p0 = *reinterpret_cast<const float4*>(&sh.c.v[vi][0]);
            float4 p1 = *reinterpret_cast<const float4*>(&sh.c.v[vi][4]);
            float xv[N_F] = {p0.x, p0.y, p0.z, p0.w, p1.x, p1.y, p1.z, p1.w};

            float a[N_F];
#pragma unroll
            for (int f = 0; f < N_F; f++) a[f] = fabsf(xu[f] - xv[f]);

            int k = 0;
#pragma unroll
            for (int i = 0; i < N_F; i++)
#pragma unroll
                for (int j = i; j < N_F; j++) {
                    acc[k] = fmaf(a[i], a[j], acc[k]);
                    k++;
                }
        }

        // Diagonal tiles are internally symmetric: weight 0.5 so each
        // unordered pair u<v counts exactly once (self terms are 0).
        const float w = (ti == tj) ? 0.5f : 1.0f;
        const int lane = tid & 31;
        const int warp = tid >> 5;
#pragma unroll
        for (int k = 0; k < NPAIR; k++) {
            float v = acc[k];
            for (int o = 16; o; o >>= 1) v += __shfl_down_sync(0xffffffffu, v, o);
            if (lane == 0) sh.c.red[warp][k] = v;
        }
        __syncthreads();
        if (tid < NPAIR) {
            float v = (sh.c.red[0][tid] + sh.c.red[1][tid]
                     + sh.c.red[2][tid] + sh.c.red[3][tid]) * w;
            atomicAdd(&g_stot[NPAIR + tid], v);
        }
    } else {
        // ---------------- rowsum path ----------------
        const int rb = bid - NCROSSB;      // [0, 512)
        const int f = rb >> 6;             // 0..7
        const int ut = (rb >> 1) & 31;     // u-tile
        const int half = rb & 1;           // v-half
        const float* xf = x + f * C_DIM;
        const int vb = half * 2048;

        for (int i = tid; i < 2048; i += 128) sh.row[i] = -xf[vb + i];

        const int u = ut * 128 + tid;
        const float xu = xf[u];
        __syncthreads();

        float r0 = 0.f, r1 = 0.f, r2 = 0.f, r3 = 0.f;
        const float4* row4 = (const float4*)sh.row;
#pragma unroll 4
        for (int p = 0; p < 512; p++) {
            float4 q = row4[p];
            r0 += fabsf(xu + q.x);
            r1 += fabsf(xu + q.y);
            r2 += fabsf(xu + q.z);
            r3 += fabsf(xu + q.w);
        }
        g_rowsum2[half][f * C_DIM + u] = (r0 + r1) + (r2 + r3);
    }
}

// ============================ epilogue kernel ============================
// 32 blocks x 128 threads: block b = u-tile of 128; last block does final math.
__global__ __launch_bounds__(128) void reduce_kernel(float* __restrict__ out) {
    __shared__ float red[4][NPAIR + N_F];
    __shared__ float sdc[NPAIR];
    __shared__ float sm[N_F];
    __shared__ unsigned sh_rank;

    const int tid = threadIdx.x;
    const int lane = tid & 31;
    const int warp = tid >> 5;
    const int u = blockIdx.x * 128 + tid;

    float r[N_F];
#pragma unroll
    for (int f = 0; f < N_F; f++)
        r[f] = g_rowsum2[0][f * C_DIM + u] + g_rowsum2[1][f * C_DIM + u];

    float dot[NPAIR];
    {
        int k = 0;
#pragma unroll
        for (int i = 0; i < N_F; i++)
#pragma unroll
            for (int j = i; j < N_F; j++) {
                dot[k] = r[i] * r[j];
                k++;
            }
    }

#pragma unroll
    for (int k = 0; k < NPAIR; k++) {
        float v = dot[k];
        for (int o = 16; o; o >>= 1) v += __shfl_down_sync(0xffffffffu, v, o);
        if (lane == 0) red[warp][k] = v;
    }
#pragma unroll
    for (int f = 0; f < N_F; f++) {
        float v = r[f];
        for (int o = 16; o; o >>= 1) v += __shfl_down_sync(0xffffffffu, v, o);
        if (lane == 0) red[warp][NPAIR + f] = v;
    }
    __syncthreads();
    if (tid < NPAIR + N_F) {
        float v = red[0][tid] + red[1][tid] + red[2][tid] + red[3][tid];
        int dst = (tid < NPAIR) ? tid : (2 * NPAIR + (tid - NPAIR));
        atomicAdd(&g_stot[dst], v);
    }

    // Ticket: last block to finish runs the final 8x8 math.
    __threadfence();
    if (tid == 0) sh_rank = atomicAdd(&g_ctr, 1);
    __syncthreads();
    if (sh_rank != 31) return;

    const float fC = (float)C_DIM;
    const float invC2 = 1.0f / (fC * fC);

    if (tid < N_F) sm[tid] = __ldcg(&g_stot[2 * NPAIR + tid]) * invC2;
    __syncthreads();

    if (tid < NPAIR) {
        // k -> (i, j)
        int kk = tid, i = 0;
        while (kk >= N_F - i) { kk -= N_F - i; i++; }
        int j = i + kk;
        // S = 2*cross_tri/C^2 - 2*rowdot/C^3 + m_i*m_j
        float s = 2.0f * __ldcg(&g_stot[NPAIR + tid]) * invC2
                - 2.0f * __ldcg(&g_stot[tid]) * invC2 / fC
                + sm[i] * sm[j];
        sdc[tid] = sqrtf(fmaxf(s, 0.0f) + EPS_F);
    }
    __syncthreads();

    if (tid == 0) {
        float cor = 0.0f;
        for (int i = 0; i < N_F; i++) {
            int di = i * N_F - (i * (i - 1)) / 2;       // k(i,i)
            for (int j = i + 1; j < N_F; j++) {
                int dj = j * N_F - (j * (j - 1)) / 2;   // k(j,j)
                int kij = di + (j - i);                  // k(i,j)
                cor += sdc[kij] / sqrtf(sdc[di] * sdc[dj] + EPS_F);
            }
        }
        out[0] = cor;
    }
    __syncthreads();

    // Reset scratch for the next graph replay (reads are all done above).
    if (tid < NSTOT) g_stot[tid] = 0.0f;
    if (tid == 0) g_ctr = 0;
}

extern "C" void kernel_launch(void* const* d_in, const int* in_sizes, int n_in,
                              void* d_out, int out_size) {
    const float* x = (const float*)d_in[0];
    float* out = (float*)d_out;

    main_kernel<<<NBLOCKS, 128>>>(x);
    reduce_kernel<<<32, 128>>>(out);
}